// round 1
// baseline (speedup 1.0000x reference)
#include <cuda_runtime.h>
#include <cuda_bf16.h>
#include <cstdint>

// ---------------------------------------------------------------------------
// Problem constants
// ---------------------------------------------------------------------------
#define BATCH   2
#define SEQ     2048
#define DMODEL  1024
#define DINNER  2048
#define DSTATE  16
#define DCONV   4
#define DTRANK  64
#define MROWS   (BATCH * SEQ)          // 4096
#define XZCOLS  (2 * DINNER)           // 4096
#define XDBLC   (DTRANK + 2 * DSTATE)  // 96

// ---------------------------------------------------------------------------
// Scratch (device globals; no runtime allocation allowed)
// ---------------------------------------------------------------------------
__device__ float g_xz  [(size_t)MROWS * XZCOLS];   // 64 MB: [xi | z]
__device__ float g_xc  [(size_t)MROWS * DINNER];   // 32 MB: conv+silu output
__device__ float g_xdbl[(size_t)MROWS * XDBLC];    // 1.5 MB: [dt_r | B | C]
__device__ float g_dt  [(size_t)MROWS * DINNER];   // 32 MB: softplus(dt)
__device__ float g_y   [(size_t)MROWS * DINNER];   // 32 MB: scan output (gated)
__device__ float g_h   [(size_t)MROWS * DMODEL];   // 16 MB: out_proj + residual

// ---------------------------------------------------------------------------
// Generic NT SGEMM:  C[M,N] = A[M,K] * B[N,K]^T   (both row-major, K fastest)
// Epilogues: 0 = plain, 1 = softplus(acc + bias[n]), 2 = acc + res[m*ldc+n]
// ---------------------------------------------------------------------------
enum { EPI_PLAIN = 0, EPI_SOFTPLUS = 1, EPI_RES = 2 };

template <int BM, int BN, int BK, int TM, int TN, int EPI>
__global__ __launch_bounds__((BM / TM) * (BN / TN))
void sgemm_nt(const float* __restrict__ A, int lda,
              const float* __restrict__ B, int ldb,
              float* __restrict__ C, int ldc,
              int M, int N, int K,
              const float* __restrict__ aux)
{
    constexpr int NT = (BM / TM) * (BN / TN);
    __shared__ float As[BK][BM];
    __shared__ float Bs[BK][BN];

    const int tid = threadIdx.x;
    const int tx  = tid % (BN / TN);   // n direction
    const int ty  = tid / (BN / TN);   // m direction
    const int m0  = blockIdx.y * BM;
    const int n0  = blockIdx.x * BN;

    float acc[TM][TN];
#pragma unroll
    for (int i = 0; i < TM; i++)
#pragma unroll
        for (int j = 0; j < TN; j++) acc[i][j] = 0.f;

    const float* Ap = A + (size_t)m0 * lda;
    const float* Bp = B + (size_t)n0 * ldb;

    for (int k0 = 0; k0 < K; k0 += BK) {
        // --- load A tile (BM x BK) transposed into As, float4 on K ---
        constexpr int A4 = BM * BK / 4;
#pragma unroll
        for (int idx = tid; idx < A4; idx += NT) {
            int row = idx / (BK / 4);
            int c4  = (idx % (BK / 4)) * 4;
            float4 v = *reinterpret_cast<const float4*>(Ap + (size_t)row * lda + k0 + c4);
            As[c4 + 0][row] = v.x; As[c4 + 1][row] = v.y;
            As[c4 + 2][row] = v.z; As[c4 + 3][row] = v.w;
        }
        // --- load B tile (BN x BK) transposed into Bs (guard n) ---
        constexpr int B4 = BN * BK / 4;
#pragma unroll
        for (int idx = tid; idx < B4; idx += NT) {
            int row = idx / (BK / 4);
            int c4  = (idx % (BK / 4)) * 4;
            float4 w = make_float4(0.f, 0.f, 0.f, 0.f);
            if (n0 + row < N)
                w = *reinterpret_cast<const float4*>(Bp + (size_t)row * ldb + k0 + c4);
            Bs[c4 + 0][row] = w.x; Bs[c4 + 1][row] = w.y;
            Bs[c4 + 2][row] = w.z; Bs[c4 + 3][row] = w.w;
        }
        __syncthreads();

#pragma unroll
        for (int kk = 0; kk < BK; kk++) {
            float a[TM], b[TN];
#pragma unroll
            for (int i = 0; i < TM; i++) a[i] = As[kk][ty * TM + i];
#pragma unroll
            for (int j = 0; j < TN; j++) b[j] = Bs[kk][tx * TN + j];
#pragma unroll
            for (int i = 0; i < TM; i++)
#pragma unroll
                for (int j = 0; j < TN; j++)
                    acc[i][j] = fmaf(a[i], b[j], acc[i][j]);
        }
        __syncthreads();
    }

    // --- epilogue + store ---
#pragma unroll
    for (int i = 0; i < TM; i++) {
        int m = m0 + ty * TM + i;
        if (m >= M) continue;
#pragma unroll
        for (int j = 0; j < TN; j++) {
            int n = n0 + tx * TN + j;
            if (n >= N) continue;
            float v = acc[i][j];
            if (EPI == EPI_SOFTPLUS) {
                v += aux[n];
                v = (v > 20.f) ? v : log1pf(__expf(v));
            } else if (EPI == EPI_RES) {
                v += aux[(size_t)m * ldc + n];
            }
            C[(size_t)m * ldc + n] = v;
        }
    }
}

// ---------------------------------------------------------------------------
// Depthwise causal conv (width 4) + SiLU.  xi = g_xz[:, 0:DINNER]
// ---------------------------------------------------------------------------
__global__ __launch_bounds__(256)
void conv_silu_kernel(const float* __restrict__ conv_w,
                      const float* __restrict__ conv_b)
{
    int idx = blockIdx.x * 256 + threadIdx.x;         // m*DINNER + d
    if (idx >= MROWS * DINNER) return;
    int d = idx & (DINNER - 1);
    int m = idx >> 11;                                 // DINNER = 2048
    int l = m & (SEQ - 1);                             // SEQ = 2048
    int brow = m - l;                                  // b*SEQ

    float s = conv_b[d];
#pragma unroll
    for (int j = 0; j < DCONV; j++) {
        int ll = l + j - (DCONV - 1);
        if (ll >= 0)
            s = fmaf(conv_w[d * DCONV + j],
                     g_xz[(size_t)(brow + ll) * XZCOLS + d], s);
    }
    g_xc[idx] = s * (1.f / (1.f + __expf(-s)));        // silu
}

// ---------------------------------------------------------------------------
// Selective scan: 16 lanes per (b,d) channel, one state per lane.
// Fuses + xc*D and *silu(z), writes g_y.
// ---------------------------------------------------------------------------
__global__ __launch_bounds__(256)
void scan_kernel(const float* __restrict__ A_log,
                 const float* __restrict__ Dvec)
{
    int tid = blockIdx.x * 256 + threadIdx.x;          // 65536 threads
    int s = tid & (DSTATE - 1);
    int g = tid >> 4;                                  // 0..8191
    int d = g & (DINNER - 1);
    int b = g >> 11;

    const float As = -__expf(A_log[d * DSTATE + s]);
    const float Dd = Dvec[d];

    const size_t base = (size_t)b * SEQ;
    const float* dt_p = g_dt   + base * DINNER + d;
    const float* xc_p = g_xc   + base * DINNER + d;
    const float* bc_p = g_xdbl + base * XDBLC + DTRANK + s;
    const float* z_p  = g_xz   + base * XZCOLS + DINNER + d;
    float*       y_p  = g_y    + base * DINNER + d;

    float h = 0.f;
#pragma unroll 4
    for (int t = 0; t < SEQ; t++) {
        float dt_v = dt_p[(size_t)t * DINNER];
        float x_v  = xc_p[(size_t)t * DINNER];
        float Bv   = bc_p[(size_t)t * XDBLC];
        float Cv   = bc_p[(size_t)t * XDBLC + DSTATE];

        float dA = __expf(dt_v * As);
        h = fmaf(dA, h, dt_v * Bv * x_v);
        float p = h * Cv;
        p += __shfl_xor_sync(0xffffffffu, p, 1);
        p += __shfl_xor_sync(0xffffffffu, p, 2);
        p += __shfl_xor_sync(0xffffffffu, p, 4);
        p += __shfl_xor_sync(0xffffffffu, p, 8);
        if (s == 0) {
            float zv = z_p[(size_t)t * XZCOLS];
            float y  = fmaf(Dd, x_v, p);
            y *= zv * (1.f / (1.f + __expf(-zv)));
            y_p[(size_t)t * DINNER] = y;
        }
    }
}

// ---------------------------------------------------------------------------
// LayerNorm over last dim (1024) of g_h -> out
// ---------------------------------------------------------------------------
__global__ __launch_bounds__(256)
void ln_kernel(const float* __restrict__ h,
               const float* __restrict__ gamma,
               const float* __restrict__ beta,
               float* __restrict__ out)
{
    int m = blockIdx.x;
    const float* row = h + (size_t)m * DMODEL;
    float s = 0.f, s2 = 0.f;
    for (int i = threadIdx.x; i < DMODEL; i += 256) {
        float v = row[i];
        s += v;
        s2 = fmaf(v, v, s2);
    }
#pragma unroll
    for (int o = 16; o; o >>= 1) {
        s  += __shfl_xor_sync(0xffffffffu, s,  o);
        s2 += __shfl_xor_sync(0xffffffffu, s2, o);
    }
    __shared__ float ss[8], ss2[8];
    int w = threadIdx.x >> 5, ln = threadIdx.x & 31;
    if (ln == 0) { ss[w] = s; ss2[w] = s2; }
    __syncthreads();
    s = 0.f; s2 = 0.f;
#pragma unroll
    for (int i = 0; i < 8; i++) { s += ss[i]; s2 += ss2[i]; }
    float mu  = s * (1.f / DMODEL);
    float var = s2 * (1.f / DMODEL) - mu * mu;
    float inv = rsqrtf(var + 1e-5f);
    for (int i = threadIdx.x; i < DMODEL; i += 256) {
        float v = row[i];
        out[(size_t)m * DMODEL + i] = (v - mu) * inv * gamma[i] + beta[i];
    }
}

// ---------------------------------------------------------------------------
// Launch
// ---------------------------------------------------------------------------
extern "C" void kernel_launch(void* const* d_in, const int* in_sizes, int n_in,
                              void* d_out, int out_size)
{
    const float* x          = (const float*)d_in[0];
    const float* in_proj_w  = (const float*)d_in[1];
    const float* conv_w     = (const float*)d_in[2];
    const float* conv_b     = (const float*)d_in[3];
    const float* x_proj_w   = (const float*)d_in[4];
    const float* dt_proj_w  = (const float*)d_in[5];
    const float* dt_proj_b  = (const float*)d_in[6];
    const float* A_log      = (const float*)d_in[7];
    const float* Dvec       = (const float*)d_in[8];
    const float* out_proj_w = (const float*)d_in[9];
    const float* ln_gamma   = (const float*)d_in[10];
    const float* ln_beta    = (const float*)d_in[11];
    float* out = (float*)d_out;

    float *p_xz, *p_xc, *p_xdbl, *p_dt, *p_y, *p_h;
    cudaGetSymbolAddress((void**)&p_xz,   g_xz);
    cudaGetSymbolAddress((void**)&p_xc,   g_xc);
    cudaGetSymbolAddress((void**)&p_xdbl, g_xdbl);
    cudaGetSymbolAddress((void**)&p_dt,   g_dt);
    cudaGetSymbolAddress((void**)&p_y,    g_y);
    cudaGetSymbolAddress((void**)&p_h,    g_h);

    // 1) in_proj: xz = x @ W_in^T        (4096 x 4096, K=1024)
    sgemm_nt<128, 128, 16, 8, 8, EPI_PLAIN>
        <<<dim3(XZCOLS / 128, MROWS / 128), 256>>>(
            x, DMODEL, in_proj_w, DMODEL, p_xz, XZCOLS,
            MROWS, XZCOLS, DMODEL, nullptr);

    // 2) depthwise conv + silu -> xc
    conv_silu_kernel<<<(MROWS * DINNER + 255) / 256, 256>>>(conv_w, conv_b);

    // 3) x_dbl = xc @ W_xproj^T          (4096 x 96, K=2048)
    sgemm_nt<32, 96, 16, 4, 6, EPI_PLAIN>
        <<<dim3(1, MROWS / 32), 128>>>(
            p_xc, DINNER, x_proj_w, DINNER, p_xdbl, XDBLC,
            MROWS, XDBLC, DINNER, nullptr);

    // 4) dt = softplus(x_dbl[:, :64] @ W_dt^T + b)   (4096 x 2048, K=64)
    sgemm_nt<128, 128, 16, 8, 8, EPI_SOFTPLUS>
        <<<dim3(DINNER / 128, MROWS / 128), 256>>>(
            p_xdbl, XDBLC, dt_proj_w, DTRANK, p_dt, DINNER,
            MROWS, DINNER, DTRANK, dt_proj_b);

    // 5) selective scan (+ D-skip, * silu(z)) -> y
    scan_kernel<<<(BATCH * DINNER * DSTATE) / 256, 256>>>(A_log, Dvec);

    // 6) out_proj + residual: h = y @ W_out^T + x    (4096 x 1024, K=2048)
    sgemm_nt<128, 128, 16, 8, 8, EPI_RES>
        <<<dim3(DMODEL / 128, MROWS / 128), 256>>>(
            p_y, DINNER, out_proj_w, DINNER, p_h, DMODEL,
            MROWS, DMODEL, DINNER, x);

    // 7) LayerNorm -> out
    ln_kernel<<<MROWS, 256>>>(p_h, ln_gamma, ln_beta, out);
}

// round 2
// speedup vs baseline: 1.3108x; 1.3108x over previous
#include <cuda_runtime.h>
#include <cuda_bf16.h>
#include <cstdint>

// ---------------------------------------------------------------------------
// Problem constants
// ---------------------------------------------------------------------------
#define BATCH   2
#define SEQ     2048
#define DMODEL  1024
#define DINNER  2048
#define DSTATE  16
#define DCONV   4
#define DTRANK  64
#define MROWS   (BATCH * SEQ)          // 4096
#define XZCOLS  (2 * DINNER)           // 4096
#define XDBLC   (DTRANK + 2 * DSTATE)  // 96

// ---------------------------------------------------------------------------
// Scratch (device globals; no runtime allocation allowed)
// ---------------------------------------------------------------------------
__device__ float g_xz  [(size_t)MROWS * XZCOLS];   // [xi | z]
__device__ float g_xc  [(size_t)MROWS * DINNER];   // conv+silu output
__device__ float g_xdbl[(size_t)MROWS * XDBLC];    // [dt_r | B | C]
__device__ float g_dt  [(size_t)MROWS * DINNER];   // softplus(dt)
__device__ float g_y   [(size_t)MROWS * DINNER];   // scan output (gated)
__device__ float g_h   [(size_t)MROWS * DMODEL];   // out_proj + residual

enum { EPI_PLAIN = 0, EPI_SOFTPLUS = 1, EPI_RES = 2 };

__device__ __forceinline__ uint32_t f2tf32(float f) {
    uint32_t r;
    asm("cvt.rna.tf32.f32 %0, %1;" : "=r"(r) : "f"(f));
    return r;
}

// ---------------------------------------------------------------------------
// Tensor-core NT GEMM (tf32 mma.sync): C[M,N] = A[M,K]*B[N,K]^T, row-major.
// BM=BN=128, BK=16. 256 threads = 8 warps; warp tile 32(m) x 64(n).
// Requires: M%128==0, N%128==0, K%16==0 (true for all call sites).
// ---------------------------------------------------------------------------
template <int EPI>
__global__ __launch_bounds__(256)
void mma_gemm_nt(const float* __restrict__ A, int lda,
                 const float* __restrict__ B, int ldb,
                 float* __restrict__ C, int ldc,
                 int K, const float* __restrict__ aux)
{
    constexpr int BK = 16, BKP = 20;   // pad to 20 floats (80B = 5x16B, aligned)
    __shared__ __align__(16) uint32_t As[2][128][BKP];
    __shared__ __align__(16) uint32_t Bs[2][128][BKP];

    const int tid  = threadIdx.x;
    const int lane = tid & 31;
    const int wid  = tid >> 5;
    const int g    = lane >> 2;       // 0..7
    const int tig  = lane & 3;        // 0..3
    const int wm   = wid & 3;         // 4 warps along m
    const int wn   = wid >> 2;        // 2 warps along n
    const int m0   = blockIdx.y * 128;
    const int n0   = blockIdx.x * 128;

    // global load mapping: each thread owns (row, row+64) x 4 consecutive k
    const int kq  = tid & 3;          // which float4 along k
    const int row = tid >> 2;         // 0..63

    const float* Ar0 = A + (size_t)(m0 + row)      * lda + kq * 4;
    const float* Ar1 = A + (size_t)(m0 + row + 64) * lda + kq * 4;
    const float* Br0 = B + (size_t)(n0 + row)      * ldb + kq * 4;
    const float* Br1 = B + (size_t)(n0 + row + 64) * ldb + kq * 4;

    float acc[2][8][4];
#pragma unroll
    for (int mi = 0; mi < 2; mi++)
#pragma unroll
        for (int nj = 0; nj < 8; nj++)
#pragma unroll
            for (int q = 0; q < 4; q++) acc[mi][nj][q] = 0.f;

    float4 na0, na1, nb0, nb1;

    auto sts_tile = [&](int b) {
        uint4 c;
        c.x = f2tf32(na0.x); c.y = f2tf32(na0.y); c.z = f2tf32(na0.z); c.w = f2tf32(na0.w);
        *reinterpret_cast<uint4*>(&As[b][row][kq * 4]) = c;
        c.x = f2tf32(na1.x); c.y = f2tf32(na1.y); c.z = f2tf32(na1.z); c.w = f2tf32(na1.w);
        *reinterpret_cast<uint4*>(&As[b][row + 64][kq * 4]) = c;
        c.x = f2tf32(nb0.x); c.y = f2tf32(nb0.y); c.z = f2tf32(nb0.z); c.w = f2tf32(nb0.w);
        *reinterpret_cast<uint4*>(&Bs[b][row][kq * 4]) = c;
        c.x = f2tf32(nb1.x); c.y = f2tf32(nb1.y); c.z = f2tf32(nb1.z); c.w = f2tf32(nb1.w);
        *reinterpret_cast<uint4*>(&Bs[b][row + 64][kq * 4]) = c;
    };

    // prologue: tile 0
    na0 = *reinterpret_cast<const float4*>(Ar0);
    na1 = *reinterpret_cast<const float4*>(Ar1);
    nb0 = *reinterpret_cast<const float4*>(Br0);
    nb1 = *reinterpret_cast<const float4*>(Br1);
    sts_tile(0);
    __syncthreads();

    const int NK = K / BK;
    int buf = 0;
    for (int t = 0; t < NK; t++) {
        if (t + 1 < NK) {
            int off = (t + 1) * BK;
            na0 = *reinterpret_cast<const float4*>(Ar0 + off);
            na1 = *reinterpret_cast<const float4*>(Ar1 + off);
            nb0 = *reinterpret_cast<const float4*>(Br0 + off);
            nb1 = *reinterpret_cast<const float4*>(Br1 + off);
        }

#pragma unroll
        for (int kk = 0; kk < BK; kk += 8) {
            uint32_t af[2][4];
#pragma unroll
            for (int mi = 0; mi < 2; mi++) {
                int m = wm * 32 + mi * 16 + g;
                af[mi][0] = As[buf][m][kk + tig];
                af[mi][1] = As[buf][m + 8][kk + tig];
                af[mi][2] = As[buf][m][kk + tig + 4];
                af[mi][3] = As[buf][m + 8][kk + tig + 4];
            }
            uint32_t bfr[8][2];
#pragma unroll
            for (int nj = 0; nj < 8; nj++) {
                int n = wn * 64 + nj * 8 + g;
                bfr[nj][0] = Bs[buf][n][kk + tig];
                bfr[nj][1] = Bs[buf][n][kk + tig + 4];
            }
#pragma unroll
            for (int mi = 0; mi < 2; mi++)
#pragma unroll
                for (int nj = 0; nj < 8; nj++) {
                    asm volatile(
                        "mma.sync.aligned.m16n8k8.row.col.f32.tf32.tf32.f32 "
                        "{%0,%1,%2,%3}, {%4,%5,%6,%7}, {%8,%9}, {%0,%1,%2,%3};\n"
                        : "+f"(acc[mi][nj][0]), "+f"(acc[mi][nj][1]),
                          "+f"(acc[mi][nj][2]), "+f"(acc[mi][nj][3])
                        : "r"(af[mi][0]), "r"(af[mi][1]), "r"(af[mi][2]), "r"(af[mi][3]),
                          "r"(bfr[nj][0]), "r"(bfr[nj][1]));
                }
        }

        if (t + 1 < NK) sts_tile(buf ^ 1);
        __syncthreads();
        buf ^= 1;
    }

    // ---- epilogue ----
#pragma unroll
    for (int mi = 0; mi < 2; mi++) {
#pragma unroll
        for (int nj = 0; nj < 8; nj++) {
            int m = m0 + wm * 32 + mi * 16 + g;
            int n = n0 + wn * 64 + nj * 8 + 2 * tig;
            float2 v0 = make_float2(acc[mi][nj][0], acc[mi][nj][1]);  // row m
            float2 v1 = make_float2(acc[mi][nj][2], acc[mi][nj][3]);  // row m+8
            if (EPI == EPI_SOFTPLUS) {
                float b0 = aux[n], b1 = aux[n + 1];
                v0.x += b0; v0.y += b1; v1.x += b0; v1.y += b1;
                v0.x = (v0.x > 20.f) ? v0.x : log1pf(__expf(v0.x));
                v0.y = (v0.y > 20.f) ? v0.y : log1pf(__expf(v0.y));
                v1.x = (v1.x > 20.f) ? v1.x : log1pf(__expf(v1.x));
                v1.y = (v1.y > 20.f) ? v1.y : log1pf(__expf(v1.y));
            } else if (EPI == EPI_RES) {
                float2 r0 = *reinterpret_cast<const float2*>(&aux[(size_t)m * ldc + n]);
                float2 r1 = *reinterpret_cast<const float2*>(&aux[(size_t)(m + 8) * ldc + n]);
                v0.x += r0.x; v0.y += r0.y; v1.x += r1.x; v1.y += r1.y;
            }
            *reinterpret_cast<float2*>(&C[(size_t)m * ldc + n]) = v0;
            *reinterpret_cast<float2*>(&C[(size_t)(m + 8) * ldc + n]) = v1;
        }
    }
}

// ---------------------------------------------------------------------------
// SIMT NT SGEMM for the small x_proj (N=96). 32x32 tiles, 256 threads.
// ---------------------------------------------------------------------------
template <int BM, int BN, int BK, int TM, int TN>
__global__ __launch_bounds__((BM / TM) * (BN / TN))
void sgemm_nt(const float* __restrict__ A, int lda,
              const float* __restrict__ B, int ldb,
              float* __restrict__ C, int ldc,
              int M, int N, int K)
{
    constexpr int NT = (BM / TM) * (BN / TN);
    __shared__ float As[BK][BM];
    __shared__ float Bs[BK][BN];

    const int tid = threadIdx.x;
    const int tx  = tid % (BN / TN);
    const int ty  = tid / (BN / TN);
    const int m0  = blockIdx.y * BM;
    const int n0  = blockIdx.x * BN;

    float acc[TM][TN];
#pragma unroll
    for (int i = 0; i < TM; i++)
#pragma unroll
        for (int j = 0; j < TN; j++) acc[i][j] = 0.f;

    const float* Ap = A + (size_t)m0 * lda;
    const float* Bp = B + (size_t)n0 * ldb;

    for (int k0 = 0; k0 < K; k0 += BK) {
        constexpr int A4 = BM * BK / 4;
#pragma unroll
        for (int idx = tid; idx < A4; idx += NT) {
            int r  = idx / (BK / 4);
            int c4 = (idx % (BK / 4)) * 4;
            float4 v = *reinterpret_cast<const float4*>(Ap + (size_t)r * lda + k0 + c4);
            As[c4 + 0][r] = v.x; As[c4 + 1][r] = v.y;
            As[c4 + 2][r] = v.z; As[c4 + 3][r] = v.w;
        }
        constexpr int B4 = BN * BK / 4;
#pragma unroll
        for (int idx = tid; idx < B4; idx += NT) {
            int r  = idx / (BK / 4);
            int c4 = (idx % (BK / 4)) * 4;
            float4 w = *reinterpret_cast<const float4*>(Bp + (size_t)r * ldb + k0 + c4);
            Bs[c4 + 0][r] = w.x; Bs[c4 + 1][r] = w.y;
            Bs[c4 + 2][r] = w.z; Bs[c4 + 3][r] = w.w;
        }
        __syncthreads();

#pragma unroll
        for (int kk = 0; kk < BK; kk++) {
            float a[TM], b[TN];
#pragma unroll
            for (int i = 0; i < TM; i++) a[i] = As[kk][ty * TM + i];
#pragma unroll
            for (int j = 0; j < TN; j++) b[j] = Bs[kk][tx * TN + j];
#pragma unroll
            for (int i = 0; i < TM; i++)
#pragma unroll
                for (int j = 0; j < TN; j++)
                    acc[i][j] = fmaf(a[i], b[j], acc[i][j]);
        }
        __syncthreads();
    }

#pragma unroll
    for (int i = 0; i < TM; i++) {
        int m = m0 + ty * TM + i;
#pragma unroll
        for (int j = 0; j < TN; j++) {
            int n = n0 + tx * TN + j;
            C[(size_t)m * ldc + n] = acc[i][j];
        }
    }
}

// ---------------------------------------------------------------------------
// Depthwise causal conv (width 4) + SiLU
// ---------------------------------------------------------------------------
__global__ __launch_bounds__(256)
void conv_silu_kernel(const float* __restrict__ conv_w,
                      const float* __restrict__ conv_b)
{
    int idx = blockIdx.x * 256 + threadIdx.x;
    if (idx >= MROWS * DINNER) return;
    int d = idx & (DINNER - 1);
    int m = idx >> 11;
    int l = m & (SEQ - 1);
    int brow = m - l;

    float s = conv_b[d];
#pragma unroll
    for (int j = 0; j < DCONV; j++) {
        int ll = l + j - (DCONV - 1);
        if (ll >= 0)
            s = fmaf(conv_w[d * DCONV + j],
                     g_xz[(size_t)(brow + ll) * XZCOLS + d], s);
    }
    g_xc[idx] = s * (1.f / (1.f + __expf(-s)));
}

// ---------------------------------------------------------------------------
// Selective scan: 16 lanes per (b,d); fuses D-skip and silu(z) gate
// ---------------------------------------------------------------------------
__global__ __launch_bounds__(256)
void scan_kernel(const float* __restrict__ A_log,
                 const float* __restrict__ Dvec)
{
    int tid = blockIdx.x * 256 + threadIdx.x;
    int s = tid & (DSTATE - 1);
    int g = tid >> 4;
    int d = g & (DINNER - 1);
    int b = g >> 11;

    const float As = -__expf(A_log[d * DSTATE + s]);
    const float Dd = Dvec[d];

    const size_t base = (size_t)b * SEQ;
    const float* dt_p = g_dt   + base * DINNER + d;
    const float* xc_p = g_xc   + base * DINNER + d;
    const float* bc_p = g_xdbl + base * XDBLC + DTRANK + s;
    const float* z_p  = g_xz   + base * XZCOLS + DINNER + d;
    float*       y_p  = g_y    + base * DINNER + d;

    float h = 0.f;
#pragma unroll 4
    for (int t = 0; t < SEQ; t++) {
        float dt_v = dt_p[(size_t)t * DINNER];
        float x_v  = xc_p[(size_t)t * DINNER];
        float Bv   = bc_p[(size_t)t * XDBLC];
        float Cv   = bc_p[(size_t)t * XDBLC + DSTATE];

        float dA = __expf(dt_v * As);
        h = fmaf(dA, h, dt_v * Bv * x_v);
        float p = h * Cv;
        p += __shfl_xor_sync(0xffffffffu, p, 1);
        p += __shfl_xor_sync(0xffffffffu, p, 2);
        p += __shfl_xor_sync(0xffffffffu, p, 4);
        p += __shfl_xor_sync(0xffffffffu, p, 8);
        if (s == 0) {
            float zv = z_p[(size_t)t * XZCOLS];
            float y  = fmaf(Dd, x_v, p);
            y *= zv * (1.f / (1.f + __expf(-zv)));
            y_p[(size_t)t * DINNER] = y;
        }
    }
}

// ---------------------------------------------------------------------------
// LayerNorm over last dim (1024)
// ---------------------------------------------------------------------------
__global__ __launch_bounds__(256)
void ln_kernel(const float* __restrict__ h,
               const float* __restrict__ gamma,
               const float* __restrict__ beta,
               float* __restrict__ out)
{
    int m = blockIdx.x;
    const float* row = h + (size_t)m * DMODEL;
    float s = 0.f, s2 = 0.f;
    for (int i = threadIdx.x; i < DMODEL; i += 256) {
        float v = row[i];
        s += v;
        s2 = fmaf(v, v, s2);
    }
#pragma unroll
    for (int o = 16; o; o >>= 1) {
        s  += __shfl_xor_sync(0xffffffffu, s,  o);
        s2 += __shfl_xor_sync(0xffffffffu, s2, o);
    }
    __shared__ float ss[8], ss2[8];
    int w = threadIdx.x >> 5, ln = threadIdx.x & 31;
    if (ln == 0) { ss[w] = s; ss2[w] = s2; }
    __syncthreads();
    s = 0.f; s2 = 0.f;
#pragma unroll
    for (int i = 0; i < 8; i++) { s += ss[i]; s2 += ss2[i]; }
    float mu  = s * (1.f / DMODEL);
    float var = s2 * (1.f / DMODEL) - mu * mu;
    float inv = rsqrtf(var + 1e-5f);
    for (int i = threadIdx.x; i < DMODEL; i += 256) {
        float v = row[i];
        out[(size_t)m * DMODEL + i] = (v - mu) * inv * gamma[i] + beta[i];
    }
}

// ---------------------------------------------------------------------------
// Launch
// ---------------------------------------------------------------------------
extern "C" void kernel_launch(void* const* d_in, const int* in_sizes, int n_in,
                              void* d_out, int out_size)
{
    const float* x          = (const float*)d_in[0];
    const float* in_proj_w  = (const float*)d_in[1];
    const float* conv_w     = (const float*)d_in[2];
    const float* conv_b     = (const float*)d_in[3];
    const float* x_proj_w   = (const float*)d_in[4];
    const float* dt_proj_w  = (const float*)d_in[5];
    const float* dt_proj_b  = (const float*)d_in[6];
    const float* A_log      = (const float*)d_in[7];
    const float* Dvec       = (const float*)d_in[8];
    const float* out_proj_w = (const float*)d_in[9];
    const float* ln_gamma   = (const float*)d_in[10];
    const float* ln_beta    = (const float*)d_in[11];
    float* out = (float*)d_out;

    float *p_xz, *p_xc, *p_xdbl, *p_dt, *p_y, *p_h;
    cudaGetSymbolAddress((void**)&p_xz,   g_xz);
    cudaGetSymbolAddress((void**)&p_xc,   g_xc);
    cudaGetSymbolAddress((void**)&p_xdbl, g_xdbl);
    cudaGetSymbolAddress((void**)&p_dt,   g_dt);
    cudaGetSymbolAddress((void**)&p_y,    g_y);
    cudaGetSymbolAddress((void**)&p_h,    g_h);

    // 1) in_proj: xz = x @ W_in^T   (4096 x 4096, K=1024) — tensor cores
    mma_gemm_nt<EPI_PLAIN><<<dim3(XZCOLS / 128, MROWS / 128), 256>>>(
        x, DMODEL, in_proj_w, DMODEL, p_xz, XZCOLS, DMODEL, nullptr);

    // 2) depthwise conv + silu -> xc
    conv_silu_kernel<<<(MROWS * DINNER + 255) / 256, 256>>>(conv_w, conv_b);

    // 3) x_dbl = xc @ W_xproj^T     (4096 x 96, K=2048) — SIMT
    sgemm_nt<32, 32, 16, 2, 2><<<dim3(XDBLC / 32, MROWS / 32), 256>>>(
        p_xc, DINNER, x_proj_w, DINNER, p_xdbl, XDBLC,
        MROWS, XDBLC, DINNER);

    // 4) dt = softplus(x_dbl[:, :64] @ W_dt^T + b)  (4096 x 2048, K=64)
    mma_gemm_nt<EPI_SOFTPLUS><<<dim3(DINNER / 128, MROWS / 128), 256>>>(
        p_xdbl, XDBLC, dt_proj_w, DTRANK, p_dt, DINNER, DTRANK, dt_proj_b);

    // 5) selective scan (+ D-skip, * silu(z)) -> y
    scan_kernel<<<(BATCH * DINNER * DSTATE) / 256, 256>>>(A_log, Dvec);

    // 6) out_proj + residual: h = y @ W_out^T + x   (4096 x 1024, K=2048)
    mma_gemm_nt<EPI_RES><<<dim3(DMODEL / 128, MROWS / 128), 256>>>(
        p_y, DINNER, out_proj_w, DINNER, p_h, DMODEL, DINNER, x);

    // 7) LayerNorm -> out
    ln_kernel<<<MROWS, 256>>>(p_h, ln_gamma, ln_beta, out);
}

// round 3
// speedup vs baseline: 3.1648x; 2.4144x over previous
#include <cuda_runtime.h>
#include <cuda_bf16.h>
#include <cstdint>

// ---------------------------------------------------------------------------
// Problem constants
// ---------------------------------------------------------------------------
#define BATCH   2
#define SEQ     2048
#define DMODEL  1024
#define DINNER  2048
#define DSTATE  16
#define DCONV   4
#define DTRANK  64
#define MROWS   (BATCH * SEQ)          // 4096
#define XZCOLS  (2 * DINNER)           // 4096
#define XDBLC   (DTRANK + 2 * DSTATE)  // 96

// ---------------------------------------------------------------------------
// Scratch (device globals; no runtime allocation allowed)
// ---------------------------------------------------------------------------
__device__ float g_xz  [(size_t)MROWS * XZCOLS];   // [xi | z]
__device__ float g_xc  [(size_t)MROWS * DINNER];   // conv+silu output
__device__ float g_xdbl[(size_t)MROWS * XDBLC];    // [dt_r | B | C]
__device__ float g_dt  [(size_t)MROWS * DINNER];   // softplus(dt)
__device__ float g_y   [(size_t)MROWS * DINNER];   // scan output (gated)
__device__ float g_h   [(size_t)MROWS * DMODEL];   // out_proj + residual

enum { EPI_PLAIN = 0, EPI_SOFTPLUS = 1, EPI_RES = 2 };

__device__ __forceinline__ uint32_t f2tf32(float f) {
    uint32_t r;
    asm("cvt.rna.tf32.f32 %0, %1;" : "=r"(r) : "f"(f));
    return r;
}

// ---------------------------------------------------------------------------
// Tensor-core NT GEMM (tf32 mma.sync): C[M,N] = A[M,K]*B[N,K]^T, row-major.
// BM=128, BN in {128, 96}. 256 threads = 8 warps (4 m x 2 n).
// Requires: M%128==0, K%16==0, N == gridDim.x*BN.
// ---------------------------------------------------------------------------
template <int EPI, int BN>
__global__ __launch_bounds__(256)
void mma_gemm_nt(const float* __restrict__ A, int lda,
                 const float* __restrict__ B, int ldb,
                 float* __restrict__ C, int ldc,
                 int K, const float* __restrict__ aux)
{
    constexpr int BK = 16, BKP = 20;   // pad rows to 20 words
    constexpr int WN = BN / 2;         // warp n-extent
    constexpr int NJ = BN / 16;        // 8-wide n tiles per warp
    __shared__ __align__(16) uint32_t As[2][128][BKP];
    __shared__ __align__(16) uint32_t Bs[2][BN][BKP];

    const int tid  = threadIdx.x;
    const int lane = tid & 31;
    const int wid  = tid >> 5;
    const int g    = lane >> 2;       // 0..7
    const int tig  = lane & 3;        // 0..3
    const int wm   = wid & 3;         // 4 warps along m
    const int wn   = wid >> 2;        // 2 warps along n
    const int m0   = blockIdx.y * 128;
    const int n0   = blockIdx.x * BN;

    const int kq  = tid & 3;          // which float4 along k
    const int row = tid >> 2;         // 0..63

    const float* Ar0 = A + (size_t)(m0 + row)      * lda + kq * 4;
    const float* Ar1 = A + (size_t)(m0 + row + 64) * lda + kq * 4;
    const float* Br0 = B + (size_t)(n0 + row)      * ldb + kq * 4;
    const float* Br1 = B + (size_t)(n0 + row + 64) * ldb + kq * 4;
    const bool b1ok = (row + 64 < BN);

    float acc[2][NJ][4];
#pragma unroll
    for (int mi = 0; mi < 2; mi++)
#pragma unroll
        for (int nj = 0; nj < NJ; nj++)
#pragma unroll
            for (int q = 0; q < 4; q++) acc[mi][nj][q] = 0.f;

    float4 na0, na1, nb0, nb1;

    auto sts_tile = [&](int b) {
        uint4 c;
        c.x = f2tf32(na0.x); c.y = f2tf32(na0.y); c.z = f2tf32(na0.z); c.w = f2tf32(na0.w);
        *reinterpret_cast<uint4*>(&As[b][row][kq * 4]) = c;
        c.x = f2tf32(na1.x); c.y = f2tf32(na1.y); c.z = f2tf32(na1.z); c.w = f2tf32(na1.w);
        *reinterpret_cast<uint4*>(&As[b][row + 64][kq * 4]) = c;
        if (row < BN) {
            c.x = f2tf32(nb0.x); c.y = f2tf32(nb0.y); c.z = f2tf32(nb0.z); c.w = f2tf32(nb0.w);
            *reinterpret_cast<uint4*>(&Bs[b][row][kq * 4]) = c;
        }
        if (b1ok) {
            c.x = f2tf32(nb1.x); c.y = f2tf32(nb1.y); c.z = f2tf32(nb1.z); c.w = f2tf32(nb1.w);
            *reinterpret_cast<uint4*>(&Bs[b][row + 64][kq * 4]) = c;
        }
    };
    auto ldg_tile = [&](int off) {
        na0 = *reinterpret_cast<const float4*>(Ar0 + off);
        na1 = *reinterpret_cast<const float4*>(Ar1 + off);
        if (row < BN) nb0 = *reinterpret_cast<const float4*>(Br0 + off);
        if (b1ok)     nb1 = *reinterpret_cast<const float4*>(Br1 + off);
    };

    ldg_tile(0);
    sts_tile(0);
    __syncthreads();

    const int NK = K / BK;
    int buf = 0;
    for (int t = 0; t < NK; t++) {
        if (t + 1 < NK) ldg_tile((t + 1) * BK);

#pragma unroll
        for (int kk = 0; kk < BK; kk += 8) {
            uint32_t af[2][4];
#pragma unroll
            for (int mi = 0; mi < 2; mi++) {
                int m = wm * 32 + mi * 16 + g;
                af[mi][0] = As[buf][m][kk + tig];
                af[mi][1] = As[buf][m + 8][kk + tig];
                af[mi][2] = As[buf][m][kk + tig + 4];
                af[mi][3] = As[buf][m + 8][kk + tig + 4];
            }
            uint32_t bfr[NJ][2];
#pragma unroll
            for (int nj = 0; nj < NJ; nj++) {
                int n = wn * WN + nj * 8 + g;
                bfr[nj][0] = Bs[buf][n][kk + tig];
                bfr[nj][1] = Bs[buf][n][kk + tig + 4];
            }
#pragma unroll
            for (int mi = 0; mi < 2; mi++)
#pragma unroll
                for (int nj = 0; nj < NJ; nj++) {
                    asm volatile(
                        "mma.sync.aligned.m16n8k8.row.col.f32.tf32.tf32.f32 "
                        "{%0,%1,%2,%3}, {%4,%5,%6,%7}, {%8,%9}, {%0,%1,%2,%3};\n"
                        : "+f"(acc[mi][nj][0]), "+f"(acc[mi][nj][1]),
                          "+f"(acc[mi][nj][2]), "+f"(acc[mi][nj][3])
                        : "r"(af[mi][0]), "r"(af[mi][1]), "r"(af[mi][2]), "r"(af[mi][3]),
                          "r"(bfr[nj][0]), "r"(bfr[nj][1]));
                }
        }

        if (t + 1 < NK) sts_tile(buf ^ 1);
        __syncthreads();
        buf ^= 1;
    }

    // ---- epilogue ----
#pragma unroll
    for (int mi = 0; mi < 2; mi++) {
#pragma unroll
        for (int nj = 0; nj < NJ; nj++) {
            int m = m0 + wm * 32 + mi * 16 + g;
            int n = n0 + wn * WN + nj * 8 + 2 * tig;
            float2 v0 = make_float2(acc[mi][nj][0], acc[mi][nj][1]);  // row m
            float2 v1 = make_float2(acc[mi][nj][2], acc[mi][nj][3]);  // row m+8
            if (EPI == EPI_SOFTPLUS) {
                float b0 = aux[n], b1 = aux[n + 1];
                v0.x += b0; v0.y += b1; v1.x += b0; v1.y += b1;
                v0.x = (v0.x > 20.f) ? v0.x : log1pf(__expf(v0.x));
                v0.y = (v0.y > 20.f) ? v0.y : log1pf(__expf(v0.y));
                v1.x = (v1.x > 20.f) ? v1.x : log1pf(__expf(v1.x));
                v1.y = (v1.y > 20.f) ? v1.y : log1pf(__expf(v1.y));
            } else if (EPI == EPI_RES) {
                float2 r0 = *reinterpret_cast<const float2*>(&aux[(size_t)m * ldc + n]);
                float2 r1 = *reinterpret_cast<const float2*>(&aux[(size_t)(m + 8) * ldc + n]);
                v0.x += r0.x; v0.y += r0.y; v1.x += r1.x; v1.y += r1.y;
            }
            *reinterpret_cast<float2*>(&C[(size_t)m * ldc + n]) = v0;
            *reinterpret_cast<float2*>(&C[(size_t)(m + 8) * ldc + n]) = v1;
        }
    }
}

// ---------------------------------------------------------------------------
// Depthwise causal conv (width 4) + SiLU
// ---------------------------------------------------------------------------
__global__ __launch_bounds__(256)
void conv_silu_kernel(const float* __restrict__ conv_w,
                      const float* __restrict__ conv_b)
{
    int idx = blockIdx.x * 256 + threadIdx.x;
    if (idx >= MROWS * DINNER) return;
    int d = idx & (DINNER - 1);
    int m = idx >> 11;
    int l = m & (SEQ - 1);
    int brow = m - l;

    float s = conv_b[d];
#pragma unroll
    for (int j = 0; j < DCONV; j++) {
        int ll = l + j - (DCONV - 1);
        if (ll >= 0)
            s = fmaf(conv_w[d * DCONV + j],
                     g_xz[(size_t)(brow + ll) * XZCOLS + d], s);
    }
    g_xc[idx] = s * (1.f / (1.f + __expf(-s)));
}

// ---------------------------------------------------------------------------
// SMEM-staged selective scan.
// Block: 256 threads = 16 channels x 16 states, one batch element.
// Time chunks of TC=64 staged through shared memory with register prefetch.
// Fuses + xc*D and * silu(z); stages y and writes it back coalesced.
// ---------------------------------------------------------------------------
#define TC 64
__global__ __launch_bounds__(256)
void scan_kernel(const float* __restrict__ A_log,
                 const float* __restrict__ Dvec)
{
    __shared__ __align__(16) float dt_s[TC][16];
    __shared__ __align__(16) float xc_s[TC][16];
    __shared__ __align__(16) float z_s [TC][16];
    __shared__ __align__(16) float B_s [TC][16];
    __shared__ __align__(16) float C_s [TC][16];
    __shared__ __align__(16) float y_s [TC][16];

    const int tid = threadIdx.x;
    const int s   = tid & 15;          // state
    const int c   = tid >> 4;          // channel within block (0..15)
    const int d0  = (blockIdx.x * 16) & (DINNER - 1);
    const int b   = (blockIdx.x * 16) >> 11;      // DINNER=2048
    const int d   = d0 + c;

    const float As = -__expf(A_log[d * DSTATE + s]);
    const float Dd = Dvec[d];

    // loader mapping: thread -> (row r in chunk, quad q)
    const int r = tid >> 2;            // 0..63
    const int q = tid & 3;             // 0..3

    const size_t mb = (size_t)b * SEQ;   // first row of this batch

    float4 p_dt, p_xc, p_z, p_B, p_C;
    auto ldg_chunk = [&](int t0) {
        size_t m = mb + t0 + r;
        p_dt = *reinterpret_cast<const float4*>(&g_dt [m * DINNER + d0 + q * 4]);
        p_xc = *reinterpret_cast<const float4*>(&g_xc [m * DINNER + d0 + q * 4]);
        p_z  = *reinterpret_cast<const float4*>(&g_xz [m * XZCOLS + DINNER + d0 + q * 4]);
        p_B  = *reinterpret_cast<const float4*>(&g_xdbl[m * XDBLC + DTRANK + q * 4]);
        p_C  = *reinterpret_cast<const float4*>(&g_xdbl[m * XDBLC + DTRANK + DSTATE + q * 4]);
    };
    auto sts_chunk = [&]() {
        *reinterpret_cast<float4*>(&dt_s[r][q * 4]) = p_dt;
        *reinterpret_cast<float4*>(&xc_s[r][q * 4]) = p_xc;
        *reinterpret_cast<float4*>(&z_s [r][q * 4]) = p_z;
        *reinterpret_cast<float4*>(&B_s [r][q * 4]) = p_B;
        *reinterpret_cast<float4*>(&C_s [r][q * 4]) = p_C;
    };

    ldg_chunk(0);
    sts_chunk();
    __syncthreads();

    float h = 0.f;
    for (int t0 = 0; t0 < SEQ; t0 += TC) {
        if (t0 + TC < SEQ) ldg_chunk(t0 + TC);

#pragma unroll 4
        for (int t = 0; t < TC; t++) {
            float dt_v = dt_s[t][c];
            float x_v  = xc_s[t][c];
            float Bv   = B_s [t][s];
            float Cv   = C_s [t][s];
            float dA = __expf(dt_v * As);
            h = fmaf(dA, h, dt_v * Bv * x_v);
            float p = h * Cv;
            p += __shfl_xor_sync(0xffffffffu, p, 1);
            p += __shfl_xor_sync(0xffffffffu, p, 2);
            p += __shfl_xor_sync(0xffffffffu, p, 4);
            p += __shfl_xor_sync(0xffffffffu, p, 8);
            if (s == 0) {
                float zv = z_s[t][c];
                float y  = fmaf(Dd, x_v, p);
                y *= zv * (1.f / (1.f + __expf(-zv)));
                y_s[t][c] = y;
            }
        }
        __syncthreads();                 // compute done; y_s complete

        // coalesced writeback of y chunk
        {
            size_t m = mb + t0 + r;
            *reinterpret_cast<float4*>(&g_y[m * DINNER + d0 + q * 4]) =
                *reinterpret_cast<const float4*>(&y_s[r][q * 4]);
        }
        if (t0 + TC < SEQ) sts_chunk();
        __syncthreads();                 // buffers ready for next compute
    }
}

// ---------------------------------------------------------------------------
// LayerNorm over last dim (1024)
// ---------------------------------------------------------------------------
__global__ __launch_bounds__(256)
void ln_kernel(const float* __restrict__ h,
               const float* __restrict__ gamma,
               const float* __restrict__ beta,
               float* __restrict__ out)
{
    int m = blockIdx.x;
    const float* row = h + (size_t)m * DMODEL;
    float s = 0.f, s2 = 0.f;
    for (int i = threadIdx.x; i < DMODEL; i += 256) {
        float v = row[i];
        s += v;
        s2 = fmaf(v, v, s2);
    }
#pragma unroll
    for (int o = 16; o; o >>= 1) {
        s  += __shfl_xor_sync(0xffffffffu, s,  o);
        s2 += __shfl_xor_sync(0xffffffffu, s2, o);
    }
    __shared__ float ss[8], ss2[8];
    int w = threadIdx.x >> 5, ln = threadIdx.x & 31;
    if (ln == 0) { ss[w] = s; ss2[w] = s2; }
    __syncthreads();
    s = 0.f; s2 = 0.f;
#pragma unroll
    for (int i = 0; i < 8; i++) { s += ss[i]; s2 += ss2[i]; }
    float mu  = s * (1.f / DMODEL);
    float var = s2 * (1.f / DMODEL) - mu * mu;
    float inv = rsqrtf(var + 1e-5f);
    for (int i = threadIdx.x; i < DMODEL; i += 256) {
        float v = row[i];
        out[(size_t)m * DMODEL + i] = (v - mu) * inv * gamma[i] + beta[i];
    }
}

// ---------------------------------------------------------------------------
// Launch
// ---------------------------------------------------------------------------
extern "C" void kernel_launch(void* const* d_in, const int* in_sizes, int n_in,
                              void* d_out, int out_size)
{
    const float* x          = (const float*)d_in[0];
    const float* in_proj_w  = (const float*)d_in[1];
    const float* conv_w     = (const float*)d_in[2];
    const float* conv_b     = (const float*)d_in[3];
    const float* x_proj_w   = (const float*)d_in[4];
    const float* dt_proj_w  = (const float*)d_in[5];
    const float* dt_proj_b  = (const float*)d_in[6];
    const float* A_log      = (const float*)d_in[7];
    const float* Dvec       = (const float*)d_in[8];
    const float* out_proj_w = (const float*)d_in[9];
    const float* ln_gamma   = (const float*)d_in[10];
    const float* ln_beta    = (const float*)d_in[11];
    float* out = (float*)d_out;

    float *p_xz, *p_xc, *p_xdbl, *p_dt, *p_y, *p_h;
    cudaGetSymbolAddress((void**)&p_xz,   g_xz);
    cudaGetSymbolAddress((void**)&p_xc,   g_xc);
    cudaGetSymbolAddress((void**)&p_xdbl, g_xdbl);
    cudaGetSymbolAddress((void**)&p_dt,   g_dt);
    cudaGetSymbolAddress((void**)&p_y,    g_y);
    cudaGetSymbolAddress((void**)&p_h,    g_h);

    // 1) in_proj: xz = x @ W_in^T   (4096 x 4096, K=1024)
    mma_gemm_nt<EPI_PLAIN, 128><<<dim3(XZCOLS / 128, MROWS / 128), 256>>>(
        x, DMODEL, in_proj_w, DMODEL, p_xz, XZCOLS, DMODEL, nullptr);

    // 2) depthwise conv + silu -> xc
    conv_silu_kernel<<<(MROWS * DINNER + 255) / 256, 256>>>(conv_w, conv_b);

    // 3) x_dbl = xc @ W_xproj^T     (4096 x 96, K=2048)
    mma_gemm_nt<EPI_PLAIN, 96><<<dim3(1, MROWS / 128), 256>>>(
        p_xc, DINNER, x_proj_w, DINNER, p_xdbl, XDBLC, DINNER, nullptr);

    // 4) dt = softplus(x_dbl[:, :64] @ W_dt^T + b)  (4096 x 2048, K=64)
    mma_gemm_nt<EPI_SOFTPLUS, 128><<<dim3(DINNER / 128, MROWS / 128), 256>>>(
        p_xdbl, XDBLC, dt_proj_w, DTRANK, p_dt, DINNER, DTRANK, dt_proj_b);

    // 5) SMEM-staged selective scan (+ D-skip, * silu(z)) -> y
    scan_kernel<<<(BATCH * DINNER) / 16, 256>>>(A_log, Dvec);

    // 6) out_proj + residual: h = y @ W_out^T + x   (4096 x 1024, K=2048)
    mma_gemm_nt<EPI_RES, 128><<<dim3(DMODEL / 128, MROWS / 128), 256>>>(
        p_y, DINNER, out_proj_w, DINNER, p_h, DMODEL, DINNER, x);

    // 7) LayerNorm -> out
    ln_kernel<<<MROWS, 256>>>(p_h, ln_gamma, ln_beta, out);
}

// round 4
// speedup vs baseline: 3.8172x; 1.2062x over previous
#include <cuda_runtime.h>
#include <cuda_bf16.h>
#include <cstdint>

// ---------------------------------------------------------------------------
// Problem constants
// ---------------------------------------------------------------------------
#define BATCH   2
#define SEQ     2048
#define DMODEL  1024
#define DINNER  2048
#define DSTATE  16
#define DCONV   4
#define DTRANK  64
#define MROWS   (BATCH * SEQ)          // 4096
#define XZCOLS  (2 * DINNER)           // 4096
#define XDBLC   (DTRANK + 2 * DSTATE)  // 96
#define XSPLITK 4

// ---------------------------------------------------------------------------
// Scratch (device globals; no runtime allocation allowed)
// ---------------------------------------------------------------------------
__device__ float g_xz   [(size_t)MROWS * XZCOLS];   // [xi | z]
__device__ float g_xc   [(size_t)MROWS * DINNER];   // conv+silu output
__device__ float g_xdbl [(size_t)MROWS * XDBLC];    // [dt_r | B | C]
__device__ float g_xpart[(size_t)XSPLITK * MROWS * XDBLC]; // split-K partials
__device__ float g_dt   [(size_t)MROWS * DINNER];   // softplus(dt)
__device__ float g_y    [(size_t)MROWS * DINNER];   // scan output (gated)
__device__ float g_h    [(size_t)MROWS * DMODEL];   // out_proj + residual

enum { EPI_PLAIN = 0, EPI_SOFTPLUS = 1, EPI_RES = 2 };

// ---------------------------------------------------------------------------
// PTX helpers
// ---------------------------------------------------------------------------
__device__ __forceinline__ void cp_async16(uint32_t dst, const void* src) {
    asm volatile("cp.async.cg.shared.global [%0], [%1], 16;\n" :: "r"(dst), "l"(src));
}
__device__ __forceinline__ void cp_commit() {
    asm volatile("cp.async.commit_group;\n" ::: "memory");
}
template <int N> __device__ __forceinline__ void cp_wait() {
    asm volatile("cp.async.wait_group %0;\n" :: "n"(N) : "memory");
}
__device__ __forceinline__ void ldsm_x4(uint32_t& r0, uint32_t& r1,
                                        uint32_t& r2, uint32_t& r3, uint32_t addr) {
    asm volatile("ldmatrix.sync.aligned.m8n8.x4.shared.b16 {%0,%1,%2,%3}, [%4];\n"
                 : "=r"(r0), "=r"(r1), "=r"(r2), "=r"(r3) : "r"(addr));
}

// ---------------------------------------------------------------------------
// Tensor-core NT GEMM (tf32): C[M,N] = A[M,K]*B[N,K]^T, row-major.
// BM=128, BN=128, BK=32. cp.async 3-stage pipeline, SW128 swizzle, ldmatrix.
// 256 threads = 8 warps (4 m x 2 n), warp tile 32m x 64n.
// Requires M%128==0, K%32==0. N may be < gridDim.x*128 (stores guarded,
// B row loads clamped). blockIdx.z: k-slice (A,B advance kz; C advances cz).
// ---------------------------------------------------------------------------
#define GSTAGES 3
#define STAGE_BYTES 16384   // 128 rows * 32 tf32 * 4B

template <int EPI>
__global__ __launch_bounds__(256)
void mma_gemm_nt(const float* __restrict__ A, int lda,
                 const float* __restrict__ B, int ldb,
                 float* __restrict__ C, int ldc,
                 int K, int N, const float* __restrict__ aux,
                 int kz, size_t cz)
{
    extern __shared__ __align__(16) char smem[];
    const uint32_t smem_u = (uint32_t)__cvta_generic_to_shared(smem);
    const uint32_t smA = smem_u;
    const uint32_t smB = smem_u + GSTAGES * STAGE_BYTES;

    A += (size_t)blockIdx.z * kz;
    B += (size_t)blockIdx.z * kz;
    C += (size_t)blockIdx.z * cz;

    const int tid  = threadIdx.x;
    const int lane = tid & 31;
    const int wid  = tid >> 5;
    const int g    = lane >> 2;
    const int tig  = lane & 3;
    const int wm   = wid & 3;
    const int wn   = wid >> 2;
    const int m0   = blockIdx.y * 128;
    const int n0   = blockIdx.x * 128;

    // --- cp.async source pointers / swizzled dst offsets (4 chunks/thread) ---
    const float* asrc[4];
    const float* bsrc[4];
    uint32_t soff[4];
#pragma unroll
    for (int i = 0; i < 4; i++) {
        int id = tid + i * 256;        // 0..1023
        int r  = id >> 3;              // row 0..127
        int ch = id & 7;               // 16B chunk 0..7
        soff[i] = (uint32_t)((r * 128 + ch * 16) ^ ((r & 7) << 4));
        asrc[i] = A + (size_t)(m0 + r) * lda + ch * 4;
        int br = n0 + r; if (br > N - 1) br = N - 1;   // clamp (x_proj tail)
        bsrc[i] = B + (size_t)br * ldb + ch * 4;
    }

    // --- ldmatrix per-thread addressing ---
    const int lrow  = (lane & 7) + ((lane >> 3) & 1) * 8;  // 0..15
    const int lkb   = ((lane >> 4) & 1) * 16;              // 0 or 16 bytes
    const uint32_t lmask = (uint32_t)((lane & 7) << 4);
    uint32_t abase[2], bbase[4];
#pragma unroll
    for (int mi = 0; mi < 2; mi++)
        abase[mi] = (uint32_t)((wm * 32 + mi * 16 + lrow) * 128 + lkb);
#pragma unroll
    for (int p = 0; p < 4; p++)
        bbase[p] = (uint32_t)((wn * 64 + p * 16 + lrow) * 128 + lkb);

    float acc[2][8][4];
#pragma unroll
    for (int mi = 0; mi < 2; mi++)
#pragma unroll
        for (int nj = 0; nj < 8; nj++)
#pragma unroll
            for (int q = 0; q < 4; q++) acc[mi][nj][q] = 0.f;

    const int NK = K / 32;

    auto issue = [&](int t) {
        const int s = t % GSTAGES;
        const uint32_t sa = smA + s * STAGE_BYTES;
        const uint32_t sb = smB + s * STAGE_BYTES;
        const int k0 = t * 32;
#pragma unroll
        for (int i = 0; i < 4; i++) {
            cp_async16(sa + soff[i], asrc[i] + k0);
            cp_async16(sb + soff[i], bsrc[i] + k0);
        }
    };

    // prologue: stages 0,1
    issue(0); cp_commit();
    if (NK > 1) issue(1);
    cp_commit();
    cp_wait<1>();
    __syncthreads();

    for (int t = 0; t < NK; t++) {
        const int s = t % GSTAGES;
        const uint32_t sa = smA + s * STAGE_BYTES;
        const uint32_t sb = smB + s * STAGE_BYTES;

#pragma unroll
        for (int kg = 0; kg < 4; kg++) {          // 8-k groups
            uint32_t af[2][4];
#pragma unroll
            for (int mi = 0; mi < 2; mi++)
                ldsm_x4(af[mi][0], af[mi][1], af[mi][2], af[mi][3],
                        sa + ((abase[mi] + kg * 32) ^ lmask));
            uint32_t bf[8][2];
#pragma unroll
            for (int p = 0; p < 4; p++) {
                uint32_t r0, r1, r2, r3;
                ldsm_x4(r0, r1, r2, r3, sb + ((bbase[p] + kg * 32) ^ lmask));
                bf[2 * p][0] = r0; bf[2 * p + 1][0] = r1;
                bf[2 * p][1] = r2; bf[2 * p + 1][1] = r3;
            }
#pragma unroll
            for (int mi = 0; mi < 2; mi++)
#pragma unroll
                for (int nj = 0; nj < 8; nj++) {
                    asm volatile(
                        "mma.sync.aligned.m16n8k8.row.col.f32.tf32.tf32.f32 "
                        "{%0,%1,%2,%3}, {%4,%5,%6,%7}, {%8,%9}, {%0,%1,%2,%3};\n"
                        : "+f"(acc[mi][nj][0]), "+f"(acc[mi][nj][1]),
                          "+f"(acc[mi][nj][2]), "+f"(acc[mi][nj][3])
                        : "r"(af[mi][0]), "r"(af[mi][1]), "r"(af[mi][2]), "r"(af[mi][3]),
                          "r"(bf[nj][0]), "r"(bf[nj][1]));
                }
        }

        if (t + GSTAGES - 1 < NK) issue(t + GSTAGES - 1);
        cp_commit();
        cp_wait<1>();
        __syncthreads();
    }

    // ---- epilogue ----
#pragma unroll
    for (int mi = 0; mi < 2; mi++) {
#pragma unroll
        for (int nj = 0; nj < 8; nj++) {
            int m = m0 + wm * 32 + mi * 16 + g;
            int n = n0 + wn * 64 + nj * 8 + 2 * tig;
            if (n >= N) continue;
            float2 v0 = make_float2(acc[mi][nj][0], acc[mi][nj][1]);  // row m
            float2 v1 = make_float2(acc[mi][nj][2], acc[mi][nj][3]);  // row m+8
            if (EPI == EPI_SOFTPLUS) {
                float b0 = aux[n], b1 = aux[n + 1];
                v0.x += b0; v0.y += b1; v1.x += b0; v1.y += b1;
                v0.x = (v0.x > 20.f) ? v0.x : log1pf(__expf(v0.x));
                v0.y = (v0.y > 20.f) ? v0.y : log1pf(__expf(v0.y));
                v1.x = (v1.x > 20.f) ? v1.x : log1pf(__expf(v1.x));
                v1.y = (v1.y > 20.f) ? v1.y : log1pf(__expf(v1.y));
            } else if (EPI == EPI_RES) {
                float2 r0 = *reinterpret_cast<const float2*>(&aux[(size_t)m * ldc + n]);
                float2 r1 = *reinterpret_cast<const float2*>(&aux[(size_t)(m + 8) * ldc + n]);
                v0.x += r0.x; v0.y += r0.y; v1.x += r1.x; v1.y += r1.y;
            }
            *reinterpret_cast<float2*>(&C[(size_t)m * ldc + n]) = v0;
            *reinterpret_cast<float2*>(&C[(size_t)(m + 8) * ldc + n]) = v1;
        }
    }
}

// ---------------------------------------------------------------------------
// Reduce split-K partials into g_xdbl (deterministic fixed order)
// ---------------------------------------------------------------------------
__global__ __launch_bounds__(256)
void xdbl_reduce_kernel()
{
    const int i = blockIdx.x * 256 + threadIdx.x;     // float4 index
    const int n4 = MROWS * XDBLC / 4;
    if (i >= n4) return;
    const float4* p = reinterpret_cast<const float4*>(g_xpart);
    float4 a = p[i];
    float4 b = p[i + n4];
    float4 c = p[i + 2 * n4];
    float4 d = p[i + 3 * n4];
    float4 r;
    r.x = (a.x + b.x) + (c.x + d.x);
    r.y = (a.y + b.y) + (c.y + d.y);
    r.z = (a.z + b.z) + (c.z + d.z);
    r.w = (a.w + b.w) + (c.w + d.w);
    reinterpret_cast<float4*>(g_xdbl)[i] = r;
}

// ---------------------------------------------------------------------------
// Depthwise causal conv (width 4) + SiLU
// ---------------------------------------------------------------------------
__global__ __launch_bounds__(256)
void conv_silu_kernel(const float* __restrict__ conv_w,
                      const float* __restrict__ conv_b)
{
    int idx = blockIdx.x * 256 + threadIdx.x;
    if (idx >= MROWS * DINNER) return;
    int d = idx & (DINNER - 1);
    int m = idx >> 11;
    int l = m & (SEQ - 1);
    int brow = m - l;

    float s = conv_b[d];
#pragma unroll
    for (int j = 0; j < DCONV; j++) {
        int ll = l + j - (DCONV - 1);
        if (ll >= 0)
            s = fmaf(conv_w[d * DCONV + j],
                     g_xz[(size_t)(brow + ll) * XZCOLS + d], s);
    }
    g_xc[idx] = s * (1.f / (1.f + __expf(-s)));
}

// ---------------------------------------------------------------------------
// SMEM-staged selective scan (16 channels x 16 states per block)
// ---------------------------------------------------------------------------
#define TC 64
__global__ __launch_bounds__(256)
void scan_kernel(const float* __restrict__ A_log,
                 const float* __restrict__ Dvec)
{
    __shared__ __align__(16) float dt_s[TC][16];
    __shared__ __align__(16) float xc_s[TC][16];
    __shared__ __align__(16) float z_s [TC][16];
    __shared__ __align__(16) float B_s [TC][16];
    __shared__ __align__(16) float C_s [TC][16];
    __shared__ __align__(16) float y_s [TC][16];

    const int tid = threadIdx.x;
    const int s   = tid & 15;
    const int c   = tid >> 4;
    const int d0  = (blockIdx.x * 16) & (DINNER - 1);
    const int b   = (blockIdx.x * 16) >> 11;
    const int d   = d0 + c;

    const float As = -__expf(A_log[d * DSTATE + s]);
    const float Dd = Dvec[d];

    const int r = tid >> 2;
    const int q = tid & 3;
    const size_t mb = (size_t)b * SEQ;

    float4 p_dt, p_xc, p_z, p_B, p_C;
    auto ldg_chunk = [&](int t0) {
        size_t m = mb + t0 + r;
        p_dt = *reinterpret_cast<const float4*>(&g_dt [m * DINNER + d0 + q * 4]);
        p_xc = *reinterpret_cast<const float4*>(&g_xc [m * DINNER + d0 + q * 4]);
        p_z  = *reinterpret_cast<const float4*>(&g_xz [m * XZCOLS + DINNER + d0 + q * 4]);
        p_B  = *reinterpret_cast<const float4*>(&g_xdbl[m * XDBLC + DTRANK + q * 4]);
        p_C  = *reinterpret_cast<const float4*>(&g_xdbl[m * XDBLC + DTRANK + DSTATE + q * 4]);
    };
    auto sts_chunk = [&]() {
        *reinterpret_cast<float4*>(&dt_s[r][q * 4]) = p_dt;
        *reinterpret_cast<float4*>(&xc_s[r][q * 4]) = p_xc;
        *reinterpret_cast<float4*>(&z_s [r][q * 4]) = p_z;
        *reinterpret_cast<float4*>(&B_s [r][q * 4]) = p_B;
        *reinterpret_cast<float4*>(&C_s [r][q * 4]) = p_C;
    };

    ldg_chunk(0);
    sts_chunk();
    __syncthreads();

    float h = 0.f;
    for (int t0 = 0; t0 < SEQ; t0 += TC) {
        if (t0 + TC < SEQ) ldg_chunk(t0 + TC);

#pragma unroll 4
        for (int t = 0; t < TC; t++) {
            float dt_v = dt_s[t][c];
            float x_v  = xc_s[t][c];
            float Bv   = B_s [t][s];
            float Cv   = C_s [t][s];
            float dA = __expf(dt_v * As);
            h = fmaf(dA, h, dt_v * Bv * x_v);
            float p = h * Cv;
            p += __shfl_xor_sync(0xffffffffu, p, 1);
            p += __shfl_xor_sync(0xffffffffu, p, 2);
            p += __shfl_xor_sync(0xffffffffu, p, 4);
            p += __shfl_xor_sync(0xffffffffu, p, 8);
            if (s == 0) {
                float zv = z_s[t][c];
                float y  = fmaf(Dd, x_v, p);
                y *= zv * (1.f / (1.f + __expf(-zv)));
                y_s[t][c] = y;
            }
        }
        __syncthreads();

        {
            size_t m = mb + t0 + r;
            *reinterpret_cast<float4*>(&g_y[m * DINNER + d0 + q * 4]) =
                *reinterpret_cast<const float4*>(&y_s[r][q * 4]);
        }
        if (t0 + TC < SEQ) sts_chunk();
        __syncthreads();
    }
}

// ---------------------------------------------------------------------------
// LayerNorm over last dim (1024)
// ---------------------------------------------------------------------------
__global__ __launch_bounds__(256)
void ln_kernel(const float* __restrict__ h,
               const float* __restrict__ gamma,
               const float* __restrict__ beta,
               float* __restrict__ out)
{
    int m = blockIdx.x;
    const float* row = h + (size_t)m * DMODEL;
    float s = 0.f, s2 = 0.f;
    for (int i = threadIdx.x; i < DMODEL; i += 256) {
        float v = row[i];
        s += v;
        s2 = fmaf(v, v, s2);
    }
#pragma unroll
    for (int o = 16; o; o >>= 1) {
        s  += __shfl_xor_sync(0xffffffffu, s,  o);
        s2 += __shfl_xor_sync(0xffffffffu, s2, o);
    }
    __shared__ float ss[8], ss2[8];
    int w = threadIdx.x >> 5, ln = threadIdx.x & 31;
    if (ln == 0) { ss[w] = s; ss2[w] = s2; }
    __syncthreads();
    s = 0.f; s2 = 0.f;
#pragma unroll
    for (int i = 0; i < 8; i++) { s += ss[i]; s2 += ss2[i]; }
    float mu  = s * (1.f / DMODEL);
    float var = s2 * (1.f / DMODEL) - mu * mu;
    float inv = rsqrtf(var + 1e-5f);
    for (int i = threadIdx.x; i < DMODEL; i += 256) {
        float v = row[i];
        out[(size_t)m * DMODEL + i] = (v - mu) * inv * gamma[i] + beta[i];
    }
}

// ---------------------------------------------------------------------------
// Launch
// ---------------------------------------------------------------------------
extern "C" void kernel_launch(void* const* d_in, const int* in_sizes, int n_in,
                              void* d_out, int out_size)
{
    const float* x          = (const float*)d_in[0];
    const float* in_proj_w  = (const float*)d_in[1];
    const float* conv_w     = (const float*)d_in[2];
    const float* conv_b     = (const float*)d_in[3];
    const float* x_proj_w   = (const float*)d_in[4];
    const float* dt_proj_w  = (const float*)d_in[5];
    const float* dt_proj_b  = (const float*)d_in[6];
    const float* A_log      = (const float*)d_in[7];
    const float* Dvec       = (const float*)d_in[8];
    const float* out_proj_w = (const float*)d_in[9];
    const float* ln_gamma   = (const float*)d_in[10];
    const float* ln_beta    = (const float*)d_in[11];
    float* out = (float*)d_out;

    float *p_xz, *p_xc, *p_xdbl, *p_xpart, *p_dt, *p_y, *p_h;
    cudaGetSymbolAddress((void**)&p_xz,    g_xz);
    cudaGetSymbolAddress((void**)&p_xc,    g_xc);
    cudaGetSymbolAddress((void**)&p_xdbl,  g_xdbl);
    cudaGetSymbolAddress((void**)&p_xpart, g_xpart);
    cudaGetSymbolAddress((void**)&p_dt,    g_dt);
    cudaGetSymbolAddress((void**)&p_y,     g_y);
    cudaGetSymbolAddress((void**)&p_h,     g_h);

    const int SMEM = GSTAGES * STAGE_BYTES * 2;   // 96 KB
    cudaFuncSetAttribute(mma_gemm_nt<EPI_PLAIN>,
                         cudaFuncAttributeMaxDynamicSharedMemorySize, SMEM);
    cudaFuncSetAttribute(mma_gemm_nt<EPI_SOFTPLUS>,
                         cudaFuncAttributeMaxDynamicSharedMemorySize, SMEM);
    cudaFuncSetAttribute(mma_gemm_nt<EPI_RES>,
                         cudaFuncAttributeMaxDynamicSharedMemorySize, SMEM);

    // 1) in_proj: xz = x @ W_in^T   (4096 x 4096, K=1024)
    mma_gemm_nt<EPI_PLAIN><<<dim3(XZCOLS / 128, MROWS / 128, 1), 256, SMEM>>>(
        x, DMODEL, in_proj_w, DMODEL, p_xz, XZCOLS,
        DMODEL, XZCOLS, nullptr, 0, 0);

    // 2) depthwise conv + silu -> xc
    conv_silu_kernel<<<(MROWS * DINNER + 255) / 256, 256>>>(conv_w, conv_b);

    // 3) x_dbl partials: xc @ W_xproj^T  (4096 x 96, K=2048, split-K=4)
    mma_gemm_nt<EPI_PLAIN><<<dim3(1, MROWS / 128, XSPLITK), 256, SMEM>>>(
        p_xc, DINNER, x_proj_w, DINNER, p_xpart, XDBLC,
        DINNER / XSPLITK, XDBLC, nullptr,
        DINNER / XSPLITK, (size_t)MROWS * XDBLC);

    // 3b) reduce partials -> g_xdbl
    xdbl_reduce_kernel<<<(MROWS * XDBLC / 4 + 255) / 256, 256>>>();

    // 4) dt = softplus(x_dbl[:, :64] @ W_dt^T + b)  (4096 x 2048, K=64)
    mma_gemm_nt<EPI_SOFTPLUS><<<dim3(DINNER / 128, MROWS / 128, 1), 256, SMEM>>>(
        p_xdbl, XDBLC, dt_proj_w, DTRANK, p_dt, DINNER,
        DTRANK, DINNER, dt_proj_b, 0, 0);

    // 5) SMEM-staged selective scan (+ D-skip, * silu(z)) -> y
    scan_kernel<<<(BATCH * DINNER) / 16, 256>>>(A_log, Dvec);

    // 6) out_proj + residual: h = y @ W_out^T + x   (4096 x 1024, K=2048)
    mma_gemm_nt<EPI_RES><<<dim3(DMODEL / 128, MROWS / 128, 1), 256, SMEM>>>(
        p_y, DINNER, out_proj_w, DINNER, p_h, DMODEL,
        DINNER, DMODEL, x, 0, 0);

    // 7) LayerNorm -> out
    ln_kernel<<<MROWS, 256>>>(p_h, ln_gamma, ln_beta, out);
}